// round 3
// baseline (speedup 1.0000x reference)
#include <cuda_runtime.h>
#include <cuda_bf16.h>

// Problem constants (GraphSAGE_12146167513369)
#define NN 100000
#define EE 1600000
#define FEAT 128
#define PADW 132   // smem W row stride in floats

// -------- device scratch (no allocations allowed) --------
__device__ float g_agg[NN * FEAT];   // layer-1 aggregated sum of x[src]
__device__ float g_h[NN * FEAT];     // layer-1 output (post-relu)
__device__ float g_deg[NN];          // per-dst edge counts
__device__ float g_z[NN * 2];        // z = h @ A^T (per-node, to be aggregated)
__device__ float g_s[NN * 2];        // s = h @ B^T (self term)
__device__ float g_zagg[NN * 2];     // aggregated z
__device__ float g_A[2 * FEAT];      // Wlin @ W2l
__device__ float g_B[2 * FEAT];      // Wlin @ W2r
__device__ float g_c[2];             // Wlin @ b2 + blin
__device__ int   g_is64;             // 1 if edge_index is int64, 0 if int32

// -------- dtype probe: for positive int64 values, odd int32 words are all 0 --------
__global__ void detect_kernel(const int* __restrict__ ei32) {
    if (threadIdx.x == 0 && blockIdx.x == 0) {
        int orr = 0;
        #pragma unroll
        for (int i = 1; i < 32; i += 2) orr |= ei32[i];
        g_is64 = (orr == 0) ? 1 : 0;
    }
}

__device__ __forceinline__ int edge_at(const void* ei, int is64, long long idx) {
    if (is64) return (int)((const long long*)ei)[idx];
    return ((const int*)ei)[idx];
}

// -------- tiny weight folding: A = Wlin@W2l, B = Wlin@W2r, c = Wlin@b2+blin --------
__global__ void prep_kernel(const float* __restrict__ W2l, const float* __restrict__ b2,
                            const float* __restrict__ W2r, const float* __restrict__ Wlin,
                            const float* __restrict__ blin) {
    int t = threadIdx.x;
    if (t < 256) {
        int o = t >> 7;        // 0..1
        int f = t & 127;       // 0..127
        float a = 0.f, b = 0.f;
        #pragma unroll
        for (int k = 0; k < 4; k++) {
            float w = Wlin[o * 4 + k];
            a += w * W2l[k * FEAT + f];
            b += w * W2r[k * FEAT + f];
        }
        g_A[o * FEAT + f] = a;
        g_B[o * FEAT + f] = b;
    }
    if (t < 2) {
        float c = blin[t];
        #pragma unroll
        for (int k = 0; k < 4; k++) c += Wlin[t * 4 + k] * b2[k];
        g_c[t] = c;
    }
}

// -------- zero the accumulators --------
__global__ void zero_kernel() {
    int stride = gridDim.x * blockDim.x;
    int tid = blockIdx.x * blockDim.x + threadIdx.x;
    float4* p = reinterpret_cast<float4*>(g_agg);
    for (int i = tid; i < NN * FEAT / 4; i += stride) p[i] = make_float4(0.f, 0.f, 0.f, 0.f);
    for (int i = tid; i < NN; i += stride) g_deg[i] = 0.f;
    for (int i = tid; i < NN * 2; i += stride) g_zagg[i] = 0.f;
}

// -------- layer-1 scatter: agg[dst] += x[src], deg[dst] += 1 --------
// one warp per edge; lane handles a float4 (4 channels)
__global__ void scatter1_kernel(const float* __restrict__ x,
                                const void* __restrict__ ei, int E) {
    int warp_in_block = threadIdx.x >> 5;
    int lane = threadIdx.x & 31;
    int e = blockIdx.x * (blockDim.x >> 5) + warp_in_block;
    if (e >= E) return;
    int is64 = g_is64;
    int src = edge_at(ei, is64, e);
    int dst = edge_at(ei, is64, (long long)E + e);
    const float4* xr = reinterpret_cast<const float4*>(x + (size_t)src * FEAT);
    float4 v = xr[lane];
    float* ap = g_agg + (size_t)dst * FEAT + lane * 4;
    atomicAdd(ap + 0, v.x);
    atomicAdd(ap + 1, v.y);
    atomicAdd(ap + 2, v.z);
    atomicAdd(ap + 3, v.w);
    if (lane == 0) atomicAdd(&g_deg[dst], 1.0f);
}

// -------- dense layer 1: h = relu( (agg/deg) @ W1l^T + x @ W1r^T + b1 ) --------
__global__ void dense1_kernel(const float* __restrict__ x,
                              const float* __restrict__ W1l,
                              const float* __restrict__ b1,
                              const float* __restrict__ W1r,
                              int n_nodes, int n_groups) {
    extern __shared__ float smem[];
    float* sWl = smem;                       // 128*132
    float* sWr = sWl + FEAT * PADW;          // 128*132
    float* fx  = sWr + FEAT * PADW;          // 16*128  layout [n][k]
    float* fa  = fx + 16 * FEAT;             // 16*128

    int tid = threadIdx.x;

    // stage weights once
    for (int idx = tid; idx < FEAT * FEAT; idx += blockDim.x) {
        int r = idx >> 7, cc = idx & 127;
        sWl[r * PADW + cc] = W1l[idx];
        sWr[r * PADW + cc] = W1r[idx];
    }
    __syncthreads();

    int c = tid & 127;
    int sub = tid >> 7;
    float bias = b1[c];

    for (int g = blockIdx.x; g < n_groups; g += gridDim.x) {
        int base = g * 16;
        for (int idx = tid; idx < 16 * FEAT; idx += blockDim.x) {
            int n = idx >> 7, k = idx & 127;
            int node = base + n;
            float xv = 0.f, av = 0.f;
            if (node < n_nodes) {
                xv = x[(size_t)node * FEAT + k];
                float d = fmaxf(g_deg[node], 1.0f);
                av = g_agg[(size_t)node * FEAT + k] / d;
            }
            fx[n * FEAT + k] = xv;
            fa[n * FEAT + k] = av;
        }
        __syncthreads();

        const float* fxp = fx + sub * 8 * FEAT;
        const float* fap = fa + sub * 8 * FEAT;
        float accL[8], accR[8];
        #pragma unroll
        for (int n = 0; n < 8; n++) { accL[n] = 0.f; accR[n] = 0.f; }

        #pragma unroll 4
        for (int k = 0; k < FEAT; k += 4) {
            float4 wl = *reinterpret_cast<const float4*>(&sWl[c * PADW + k]);
            float4 wr = *reinterpret_cast<const float4*>(&sWr[c * PADW + k]);
            #pragma unroll
            for (int n = 0; n < 8; n++) {
                float4 a4 = *reinterpret_cast<const float4*>(&fap[n * FEAT + k]);
                float4 x4 = *reinterpret_cast<const float4*>(&fxp[n * FEAT + k]);
                accL[n] += wl.x * a4.x + wl.y * a4.y + wl.z * a4.z + wl.w * a4.w;
                accR[n] += wr.x * x4.x + wr.y * x4.y + wr.z * x4.z + wr.w * x4.w;
            }
        }

        #pragma unroll
        for (int n = 0; n < 8; n++) {
            int node = base + sub * 8 + n;
            if (node < n_nodes)
                g_h[(size_t)node * FEAT + c] = fmaxf(accL[n] + accR[n] + bias, 0.f);
        }
        __syncthreads();
    }
}

// -------- z = h@A^T, s = h@B^T (one warp per node, warp reduction) --------
__global__ void zs_kernel(int n_nodes) {
    int w = (blockIdx.x * blockDim.x + threadIdx.x) >> 5;
    int lane = threadIdx.x & 31;
    if (w >= n_nodes) return;
    float4 hv = reinterpret_cast<const float4*>(g_h)[(size_t)w * 32 + lane];
    float4 a0 = reinterpret_cast<const float4*>(g_A)[lane];
    float4 a1 = reinterpret_cast<const float4*>(g_A)[32 + lane];
    float4 b0 = reinterpret_cast<const float4*>(g_B)[lane];
    float4 b1v = reinterpret_cast<const float4*>(g_B)[32 + lane];
    float z0 = hv.x * a0.x + hv.y * a0.y + hv.z * a0.z + hv.w * a0.w;
    float z1 = hv.x * a1.x + hv.y * a1.y + hv.z * a1.z + hv.w * a1.w;
    float s0 = hv.x * b0.x + hv.y * b0.y + hv.z * b0.z + hv.w * b0.w;
    float s1 = hv.x * b1v.x + hv.y * b1v.y + hv.z * b1v.z + hv.w * b1v.w;
    #pragma unroll
    for (int off = 16; off > 0; off >>= 1) {
        z0 += __shfl_xor_sync(0xffffffffu, z0, off);
        z1 += __shfl_xor_sync(0xffffffffu, z1, off);
        s0 += __shfl_xor_sync(0xffffffffu, s0, off);
        s1 += __shfl_xor_sync(0xffffffffu, s1, off);
    }
    if (lane == 0) {
        g_z[w * 2 + 0] = z0;
        g_z[w * 2 + 1] = z1;
        g_s[w * 2 + 0] = s0;
        g_s[w * 2 + 1] = s1;
    }
}

// -------- layer-2 scatter (only 2 floats per edge thanks to weight folding) --------
__global__ void scatter2_kernel(const void* __restrict__ ei, int E) {
    int stride = gridDim.x * blockDim.x;
    int is64 = g_is64;
    for (int e = blockIdx.x * blockDim.x + threadIdx.x; e < E; e += stride) {
        int src = edge_at(ei, is64, e);
        int dst = edge_at(ei, is64, (long long)E + e);
        atomicAdd(&g_zagg[dst * 2 + 0], g_z[src * 2 + 0]);
        atomicAdd(&g_zagg[dst * 2 + 1], g_z[src * 2 + 1]);
    }
}

// -------- epilogue: out = zagg/deg + s + c --------
__global__ void final_kernel(float* __restrict__ out, int n_nodes) {
    int stride = gridDim.x * blockDim.x;
    for (int i = blockIdx.x * blockDim.x + threadIdx.x; i < n_nodes; i += stride) {
        float d = fmaxf(g_deg[i], 1.0f);
        out[i * 2 + 0] = g_zagg[i * 2 + 0] / d + g_s[i * 2 + 0] + g_c[0];
        out[i * 2 + 1] = g_zagg[i * 2 + 1] / d + g_s[i * 2 + 1] + g_c[1];
    }
}

extern "C" void kernel_launch(void* const* d_in, const int* in_sizes, int n_in,
                              void* d_out, int out_size) {
    const float* x        = (const float*)d_in[0];
    const void*  ei       = d_in[1];
    const float* W1l      = (const float*)d_in[2];
    const float* b1       = (const float*)d_in[3];
    const float* W1r      = (const float*)d_in[4];
    const float* W2l      = (const float*)d_in[5];
    const float* b2       = (const float*)d_in[6];
    const float* W2r      = (const float*)d_in[7];
    const float* Wlin     = (const float*)d_in[8];
    const float* blin     = (const float*)d_in[9];
    float* out            = (float*)d_out;

    int n = in_sizes[0] / FEAT;       // 100000
    int E = in_sizes[1] / 2;          // 1600000
    int n_groups = (n + 15) / 16;

    size_t smem = (size_t)(2 * FEAT * PADW + 2 * 16 * FEAT) * sizeof(float);
    cudaFuncSetAttribute(dense1_kernel, cudaFuncAttributeMaxDynamicSharedMemorySize, (int)smem);

    detect_kernel<<<1, 32>>>((const int*)ei);
    prep_kernel<<<1, 256>>>(W2l, b2, W2r, Wlin, blin);
    zero_kernel<<<1024, 256>>>();
    scatter1_kernel<<<(E + 7) / 8, 256>>>(x, ei, E);
    dense1_kernel<<<592, 256, smem>>>(x, W1l, b1, W1r, n, n_groups);
    zs_kernel<<<(n * 32 + 255) / 256, 256>>>(n);
    scatter2_kernel<<<2048, 256>>>(ei, E);
    final_kernel<<<(n + 255) / 256, 256>>>(out, n);
}

// round 4
// speedup vs baseline: 2.1009x; 2.1009x over previous
#include <cuda_runtime.h>
#include <cuda_bf16.h>

#define NN 100000
#define EE 1600000
#define FEAT 128
#define PADW 132
#define SCAN_BLK 1024

// -------- device scratch --------
__device__ float g_agg[NN * FEAT];     // normalized mean-aggregated features
__device__ float g_z[NN * 2];
__device__ float g_s[NN * 2];
__device__ float g_A[2 * FEAT];
__device__ float g_B[2 * FEAT];
__device__ float g_c[2];
__device__ int   g_is64;
// CSR scratch
__device__ int g_count[NN];
__device__ int g_rowptr[NN + 1];
__device__ int g_cursor[NN];
__device__ int g_bsum[128];
__device__ int g_boff[128];
__device__ int g_srcs[EE];

// -------- dtype probe: positive int64 values have zero odd int32 words --------
__global__ void detect_kernel(const int* __restrict__ ei32) {
    if (threadIdx.x == 0) {
        int orr = 0;
        #pragma unroll
        for (int i = 1; i < 32; i += 2) orr |= ei32[i];
        g_is64 = (orr == 0) ? 1 : 0;
    }
}

__device__ __forceinline__ int edge_at(const void* ei, int is64, long long idx) {
    if (is64) return (int)((const long long*)ei)[idx];
    return ((const int*)ei)[idx];
}

// -------- weight folding --------
__global__ void prep_kernel(const float* __restrict__ W2l, const float* __restrict__ b2,
                            const float* __restrict__ W2r, const float* __restrict__ Wlin,
                            const float* __restrict__ blin) {
    int t = threadIdx.x;
    if (t < 256) {
        int o = t >> 7, f = t & 127;
        float a = 0.f, b = 0.f;
        #pragma unroll
        for (int k = 0; k < 4; k++) {
            float w = Wlin[o * 4 + k];
            a += w * W2l[k * FEAT + f];
            b += w * W2r[k * FEAT + f];
        }
        g_A[o * FEAT + f] = a;
        g_B[o * FEAT + f] = b;
    }
    if (t < 2) {
        float c = blin[t];
        #pragma unroll
        for (int k = 0; k < 4; k++) c += Wlin[t * 4 + k] * b2[k];
        g_c[t] = c;
    }
}

// -------- CSR build --------
__global__ void zero_count_kernel(int n) {
    int i = blockIdx.x * blockDim.x + threadIdx.x;
    if (i < n) g_count[i] = 0;
}

__global__ void count_kernel(const void* __restrict__ ei, int E) {
    int e = blockIdx.x * blockDim.x + threadIdx.x;
    if (e >= E) return;
    int dst = edge_at(ei, g_is64, (long long)E + e);
    atomicAdd(&g_count[dst], 1);
}

__global__ void scanA_kernel(int n) {
    __shared__ int s[SCAN_BLK];
    int t = threadIdx.x;
    int idx = blockIdx.x * SCAN_BLK + t;
    int v = (idx < n) ? g_count[idx] : 0;
    s[t] = v;
    __syncthreads();
    for (int off = 1; off < SCAN_BLK; off <<= 1) {
        int u = (t >= off) ? s[t - off] : 0;
        __syncthreads();
        s[t] += u;
        __syncthreads();
    }
    if (idx <= n) g_rowptr[idx] = s[t] - v;     // exclusive partial
    if (t == SCAN_BLK - 1) g_bsum[blockIdx.x] = s[t];
}

__global__ void scanB_kernel(int nb) {
    __shared__ int s[128];
    int t = threadIdx.x;
    int v = (t < nb) ? g_bsum[t] : 0;
    s[t] = v;
    __syncthreads();
    for (int off = 1; off < 128; off <<= 1) {
        int u = (t >= off) ? s[t - off] : 0;
        __syncthreads();
        s[t] += u;
        __syncthreads();
    }
    if (t < nb) g_boff[t] = s[t] - v;           // exclusive
}

__global__ void scanC_kernel(int n, int E) {
    int idx = blockIdx.x * SCAN_BLK + threadIdx.x;
    int off = g_boff[blockIdx.x];
    if (idx < n) {
        int r = g_rowptr[idx] + off;
        g_rowptr[idx] = r;
        g_cursor[idx] = r;
    }
    if (idx == 0) g_rowptr[n] = E;
}

__global__ void fill_kernel(const void* __restrict__ ei, int E) {
    int e = blockIdx.x * blockDim.x + threadIdx.x;
    if (e >= E) return;
    int is64 = g_is64;
    int src = edge_at(ei, is64, e);
    int dst = edge_at(ei, is64, (long long)E + e);
    int slot = atomicAdd(&g_cursor[dst], 1);
    g_srcs[slot] = src;
}

// -------- gather1: agg[n] = mean over in-neighbors of x[src]  (warp per node) --------
__global__ void gather1_kernel(const float* __restrict__ x, int n_nodes) {
    int w = (blockIdx.x * blockDim.x + threadIdx.x) >> 5;
    int lane = threadIdx.x & 31;
    if (w >= n_nodes) return;
    int beg = g_rowptr[w];
    int end = g_rowptr[w + 1];
    float4 acc = make_float4(0.f, 0.f, 0.f, 0.f);
    for (int j0 = beg; j0 < end; j0 += 32) {
        int myid = (j0 + lane < end) ? g_srcs[j0 + lane] : 0;
        int cnt = min(32, end - j0);
        for (int k = 0; k < cnt; k++) {
            int s = __shfl_sync(0xffffffffu, myid, k);
            float4 v = reinterpret_cast<const float4*>(x)[(size_t)s * 32 + lane];
            acc.x += v.x; acc.y += v.y; acc.z += v.z; acc.w += v.w;
        }
    }
    float inv = 1.0f / (float)max(end - beg, 1);
    acc.x *= inv; acc.y *= inv; acc.z *= inv; acc.w *= inv;
    reinterpret_cast<float4*>(g_agg)[(size_t)w * 32 + lane] = acc;
}

// -------- dense layer 1 fused with z/s projection --------
// h = relu(agg @ W1l^T + x @ W1r^T + b1) kept in smem; z = h@A^T, s = h@B^T written out.
__global__ void dense1_kernel(const float* __restrict__ x,
                              const float* __restrict__ W1l,
                              const float* __restrict__ b1,
                              const float* __restrict__ W1r,
                              int n_nodes, int n_groups) {
    extern __shared__ float smem[];
    float* sWl = smem;                       // 128*132
    float* sWr = sWl + FEAT * PADW;          // 128*132
    float* fx  = sWr + FEAT * PADW;          // 16*128
    float* fa  = fx + 16 * FEAT;             // 16*128 (reused as h-buffer)

    int tid = threadIdx.x;

    for (int idx = tid; idx < FEAT * FEAT; idx += blockDim.x) {
        int r = idx >> 7, cc = idx & 127;
        sWl[r * PADW + cc] = W1l[idx];
        sWr[r * PADW + cc] = W1r[idx];
    }
    __syncthreads();

    int c = tid & 127;
    int sub = tid >> 7;
    float bias = b1[c];
    int wrp = tid >> 5, lane = tid & 31;
    float4 a0 = reinterpret_cast<const float4*>(g_A)[lane];
    float4 a1 = reinterpret_cast<const float4*>(g_A)[32 + lane];
    float4 bb0 = reinterpret_cast<const float4*>(g_B)[lane];
    float4 bb1 = reinterpret_cast<const float4*>(g_B)[32 + lane];

    for (int g = blockIdx.x; g < n_groups; g += gridDim.x) {
        int base = g * 16;
        for (int idx = tid; idx < 16 * FEAT; idx += blockDim.x) {
            int n = idx >> 7, k = idx & 127;
            int node = base + n;
            float xv = 0.f, av = 0.f;
            if (node < n_nodes) {
                xv = x[(size_t)node * FEAT + k];
                av = g_agg[(size_t)node * FEAT + k];   // already normalized
            }
            fx[n * FEAT + k] = xv;
            fa[n * FEAT + k] = av;
        }
        __syncthreads();

        const float* fxp = fx + sub * 8 * FEAT;
        const float* fap = fa + sub * 8 * FEAT;
        float accL[8], accR[8];
        #pragma unroll
        for (int n = 0; n < 8; n++) { accL[n] = 0.f; accR[n] = 0.f; }

        #pragma unroll 4
        for (int k = 0; k < FEAT; k += 4) {
            float4 wl = *reinterpret_cast<const float4*>(&sWl[c * PADW + k]);
            float4 wr = *reinterpret_cast<const float4*>(&sWr[c * PADW + k]);
            #pragma unroll
            for (int n = 0; n < 8; n++) {
                float4 a4 = *reinterpret_cast<const float4*>(&fap[n * FEAT + k]);
                float4 x4 = *reinterpret_cast<const float4*>(&fxp[n * FEAT + k]);
                accL[n] += wl.x * a4.x + wl.y * a4.y + wl.z * a4.z + wl.w * a4.w;
                accR[n] += wr.x * x4.x + wr.y * x4.y + wr.z * x4.z + wr.w * x4.w;
            }
        }
        __syncthreads();   // done reading fa/fx; safe to overwrite fa with h

        #pragma unroll
        for (int n = 0; n < 8; n++) {
            int nl = sub * 8 + n;
            fa[nl * FEAT + c] = fmaxf(accL[n] + accR[n] + bias, 0.f);
        }
        __syncthreads();

        // z/s projection: warp wrp handles local nodes 2*wrp, 2*wrp+1
        #pragma unroll
        for (int q = 0; q < 2; q++) {
            int nl = wrp * 2 + q;
            int node = base + nl;
            float4 hv = reinterpret_cast<const float4*>(fa)[nl * 32 + lane];
            float z0 = hv.x * a0.x + hv.y * a0.y + hv.z * a0.z + hv.w * a0.w;
            float z1 = hv.x * a1.x + hv.y * a1.y + hv.z * a1.z + hv.w * a1.w;
            float s0 = hv.x * bb0.x + hv.y * bb0.y + hv.z * bb0.z + hv.w * bb0.w;
            float s1 = hv.x * bb1.x + hv.y * bb1.y + hv.z * bb1.z + hv.w * bb1.w;
            #pragma unroll
            for (int off = 16; off > 0; off >>= 1) {
                z0 += __shfl_xor_sync(0xffffffffu, z0, off);
                z1 += __shfl_xor_sync(0xffffffffu, z1, off);
                s0 += __shfl_xor_sync(0xffffffffu, s0, off);
                s1 += __shfl_xor_sync(0xffffffffu, s1, off);
            }
            if (lane == 0 && node < n_nodes) {
                g_z[node * 2 + 0] = z0;
                g_z[node * 2 + 1] = z1;
                g_s[node * 2 + 0] = s0;
                g_s[node * 2 + 1] = s1;
            }
        }
        __syncthreads();   // before next group's feature load
    }
}

// -------- gather2 + epilogue: out = mean(z[src]) + s + c  (warp per node) --------
__global__ void gather2_kernel(float* __restrict__ out, int n_nodes) {
    int w = (blockIdx.x * blockDim.x + threadIdx.x) >> 5;
    int lane = threadIdx.x & 31;
    if (w >= n_nodes) return;
    int beg = g_rowptr[w];
    int end = g_rowptr[w + 1];
    float acc0 = 0.f, acc1 = 0.f;
    for (int j = beg + lane; j < end; j += 32) {
        int s = g_srcs[j];
        float2 zv = reinterpret_cast<const float2*>(g_z)[s];
        acc0 += zv.x;
        acc1 += zv.y;
    }
    #pragma unroll
    for (int off = 16; off > 0; off >>= 1) {
        acc0 += __shfl_xor_sync(0xffffffffu, acc0, off);
        acc1 += __shfl_xor_sync(0xffffffffu, acc1, off);
    }
    if (lane == 0) {
        float inv = 1.0f / (float)max(end - beg, 1);
        out[w * 2 + 0] = acc0 * inv + g_s[w * 2 + 0] + g_c[0];
        out[w * 2 + 1] = acc1 * inv + g_s[w * 2 + 1] + g_c[1];
    }
}

extern "C" void kernel_launch(void* const* d_in, const int* in_sizes, int n_in,
                              void* d_out, int out_size) {
    const float* x        = (const float*)d_in[0];
    const void*  ei       = d_in[1];
    const float* W1l      = (const float*)d_in[2];
    const float* b1       = (const float*)d_in[3];
    const float* W1r      = (const float*)d_in[4];
    const float* W2l      = (const float*)d_in[5];
    const float* b2       = (const float*)d_in[6];
    const float* W2r      = (const float*)d_in[7];
    const float* Wlin     = (const float*)d_in[8];
    const float* blin     = (const float*)d_in[9];
    float* out            = (float*)d_out;

    int n = in_sizes[0] / FEAT;       // 100000
    int E = in_sizes[1] / 2;          // 1600000
    int n_groups = (n + 15) / 16;
    int nb = (n + SCAN_BLK - 1) / SCAN_BLK;   // 98

    size_t smem = (size_t)(2 * FEAT * PADW + 2 * 16 * FEAT) * sizeof(float);
    cudaFuncSetAttribute(dense1_kernel, cudaFuncAttributeMaxDynamicSharedMemorySize, (int)smem);

    detect_kernel<<<1, 32>>>((const int*)ei);
    prep_kernel<<<1, 256>>>(W2l, b2, W2r, Wlin, blin);
    zero_count_kernel<<<(n + 255) / 256, 256>>>(n);
    count_kernel<<<(E + 255) / 256, 256>>>(ei, E);
    scanA_kernel<<<nb, SCAN_BLK>>>(n);
    scanB_kernel<<<1, 128>>>(nb);
    scanC_kernel<<<nb, SCAN_BLK>>>(n, E);
    fill_kernel<<<(E + 255) / 256, 256>>>(ei, E);
    gather1_kernel<<<(n * 32 + 255) / 256, 256>>>(x, n);
    dense1_kernel<<<592, 256, smem>>>(x, W1l, b1, W1r, n, n_groups);
    gather2_kernel<<<(n * 32 + 255) / 256, 256>>>(out, n);
}

// round 5
// speedup vs baseline: 2.6565x; 1.2644x over previous
#include <cuda_runtime.h>
#include <cuda_bf16.h>

#define NN 100000
#define EE 1600000
#define FEAT 128
#define PADW 132
#define SCAN_BLK 1024

// -------- device scratch --------
__device__ float g_agg[NN * FEAT];     // normalized mean-aggregated features
__device__ float g_z[NN * 2];
__device__ float g_s[NN * 2];
__device__ float g_A[2 * FEAT];
__device__ float g_B[2 * FEAT];
__device__ float g_c[2];
__device__ int   g_is64;
// CSR scratch
__device__ int g_count[NN];
__device__ int g_rowptr[NN + 1];
__device__ int g_cursor[NN];
__device__ int g_bsum[128];
__device__ int g_boff[128];
__device__ int g_srcs[EE];

// -------- dtype probe: positive int64 values have zero odd int32 words --------
__global__ void detect_kernel(const int* __restrict__ ei32) {
    if (threadIdx.x == 0) {
        int orr = 0;
        #pragma unroll
        for (int i = 1; i < 32; i += 2) orr |= ei32[i];
        g_is64 = (orr == 0) ? 1 : 0;
    }
}

__device__ __forceinline__ int edge_at(const void* ei, int is64, long long idx) {
    if (is64) return (int)((const long long*)ei)[idx];
    return ((const int*)ei)[idx];
}

// -------- weight folding --------
__global__ void prep_kernel(const float* __restrict__ W2l, const float* __restrict__ b2,
                            const float* __restrict__ W2r, const float* __restrict__ Wlin,
                            const float* __restrict__ blin) {
    int t = threadIdx.x;
    if (t < 256) {
        int o = t >> 7, f = t & 127;
        float a = 0.f, b = 0.f;
        #pragma unroll
        for (int k = 0; k < 4; k++) {
            float w = Wlin[o * 4 + k];
            a += w * W2l[k * FEAT + f];
            b += w * W2r[k * FEAT + f];
        }
        g_A[o * FEAT + f] = a;
        g_B[o * FEAT + f] = b;
    }
    if (t < 2) {
        float c = blin[t];
        #pragma unroll
        for (int k = 0; k < 4; k++) c += Wlin[t * 4 + k] * b2[k];
        g_c[t] = c;
    }
}

// -------- CSR build --------
__global__ void zero_count_kernel(int n) {
    int i = blockIdx.x * blockDim.x + threadIdx.x;
    if (i < n) g_count[i] = 0;
}

__global__ void count_kernel(const void* __restrict__ ei, int E) {
    int e = blockIdx.x * blockDim.x + threadIdx.x;
    if (e >= E) return;
    int dst = edge_at(ei, g_is64, (long long)E + e);
    atomicAdd(&g_count[dst], 1);
}

__global__ void scanA_kernel(int n) {
    __shared__ int s[SCAN_BLK];
    int t = threadIdx.x;
    int idx = blockIdx.x * SCAN_BLK + t;
    int v = (idx < n) ? g_count[idx] : 0;
    s[t] = v;
    __syncthreads();
    for (int off = 1; off < SCAN_BLK; off <<= 1) {
        int u = (t >= off) ? s[t - off] : 0;
        __syncthreads();
        s[t] += u;
        __syncthreads();
    }
    if (idx <= n) g_rowptr[idx] = s[t] - v;
    if (t == SCAN_BLK - 1) g_bsum[blockIdx.x] = s[t];
}

__global__ void scanB_kernel(int nb) {
    __shared__ int s[128];
    int t = threadIdx.x;
    int v = (t < nb) ? g_bsum[t] : 0;
    s[t] = v;
    __syncthreads();
    for (int off = 1; off < 128; off <<= 1) {
        int u = (t >= off) ? s[t - off] : 0;
        __syncthreads();
        s[t] += u;
        __syncthreads();
    }
    if (t < nb) g_boff[t] = s[t] - v;
}

__global__ void scanC_kernel(int n, int E) {
    int idx = blockIdx.x * SCAN_BLK + threadIdx.x;
    int off = g_boff[blockIdx.x];
    if (idx < n) {
        int r = g_rowptr[idx] + off;
        g_rowptr[idx] = r;
        g_cursor[idx] = r;
    }
    if (idx == 0) g_rowptr[n] = E;
}

__global__ void fill_kernel(const void* __restrict__ ei, int E) {
    int e = blockIdx.x * blockDim.x + threadIdx.x;
    if (e >= E) return;
    int is64 = g_is64;
    int src = edge_at(ei, is64, e);
    int dst = edge_at(ei, is64, (long long)E + e);
    int slot = atomicAdd(&g_cursor[dst], 1);
    g_srcs[slot] = src;
}

// -------- gather1: agg[n] = mean over in-neighbors of x[src]  (warp per node) --------
__global__ void gather1_kernel(const float* __restrict__ x, int n_nodes) {
    int w = (blockIdx.x * blockDim.x + threadIdx.x) >> 5;
    int lane = threadIdx.x & 31;
    if (w >= n_nodes) return;
    int beg = g_rowptr[w];
    int end = g_rowptr[w + 1];
    float4 acc = make_float4(0.f, 0.f, 0.f, 0.f);
    for (int j0 = beg; j0 < end; j0 += 32) {
        int myid = (j0 + lane < end) ? g_srcs[j0 + lane] : 0;
        int cnt = min(32, end - j0);
        for (int k = 0; k < cnt; k++) {
            int s = __shfl_sync(0xffffffffu, myid, k);
            float4 v = reinterpret_cast<const float4*>(x)[(size_t)s * 32 + lane];
            acc.x += v.x; acc.y += v.y; acc.z += v.z; acc.w += v.w;
        }
    }
    float inv = 1.0f / (float)max(end - beg, 1);
    acc.x *= inv; acc.y *= inv; acc.z *= inv; acc.w *= inv;
    reinterpret_cast<float4*>(g_agg)[(size_t)w * 32 + lane] = acc;
}

// -------- dense layer 1 (register-blocked 4ch x 4nodes) fused with z/s --------
// Tile: 32 nodes x 128 channels per group. 256 threads:
//   cg = tid>>3 (0..31) -> channels {cg, cg+32, cg+64, cg+96}
//   ng = tid&7  (0..7)  -> nodes    {ng, ng+8, ng+16, ng+24}
// All smem rows padded to 132 floats -> every LDS.128 conflict-free.
__global__ void __launch_bounds__(256, 1)
dense1_kernel(const float* __restrict__ x,
              const float* __restrict__ W1l,
              const float* __restrict__ b1,
              const float* __restrict__ W1r,
              int n_nodes, int n_groups) {
    extern __shared__ float smem[];
    float* sWl = smem;                       // 128*132
    float* sWr = sWl + FEAT * PADW;          // 128*132
    float* fx  = sWr + FEAT * PADW;          // 32*132
    float* fa  = fx + 32 * PADW;             // 32*132 (reused as h buffer)

    int tid = threadIdx.x;

    // stage weights once per block
    for (int idx = tid; idx < FEAT * FEAT; idx += 256) {
        int r = idx >> 7, cc = idx & 127;
        sWl[r * PADW + cc] = W1l[idx];
        sWr[r * PADW + cc] = W1r[idx];
    }
    __syncthreads();

    int cg = tid >> 3;         // 0..31
    int ng = tid & 7;          // 0..7
    float bias[4];
    #pragma unroll
    for (int i = 0; i < 4; i++) bias[i] = b1[cg + 32 * i];

    int wrp = tid >> 5, lane = tid & 31;
    float4 a0  = reinterpret_cast<const float4*>(g_A)[lane];
    float4 a1  = reinterpret_cast<const float4*>(g_A)[32 + lane];
    float4 bb0 = reinterpret_cast<const float4*>(g_B)[lane];
    float4 bb1 = reinterpret_cast<const float4*>(g_B)[32 + lane];

    for (int g = blockIdx.x; g < n_groups; g += gridDim.x) {
        int base = g * 32;
        // load 32 nodes of x and agg (each thread: 4 float4 per array)
        for (int idx = tid; idx < 32 * 32; idx += 256) {
            int n = idx >> 5, kk = idx & 31;
            int node = base + n;
            float4 xv = make_float4(0.f, 0.f, 0.f, 0.f);
            float4 av = xv;
            if (node < n_nodes) {
                xv = reinterpret_cast<const float4*>(x)[(size_t)node * 32 + kk];
                av = reinterpret_cast<const float4*>(g_agg)[(size_t)node * 32 + kk];
            }
            *reinterpret_cast<float4*>(&fx[n * PADW + kk * 4]) = xv;
            *reinterpret_cast<float4*>(&fa[n * PADW + kk * 4]) = av;
        }
        __syncthreads();

        float acc[4][4];
        #pragma unroll
        for (int i = 0; i < 4; i++)
            #pragma unroll
            for (int j = 0; j < 4; j++) acc[i][j] = 0.f;

        #pragma unroll 2
        for (int k = 0; k < FEAT; k += 4) {
            float4 wl[4], wr[4], av[4], xv[4];
            #pragma unroll
            for (int i = 0; i < 4; i++) {
                wl[i] = *reinterpret_cast<const float4*>(&sWl[(cg + 32 * i) * PADW + k]);
                wr[i] = *reinterpret_cast<const float4*>(&sWr[(cg + 32 * i) * PADW + k]);
            }
            #pragma unroll
            for (int j = 0; j < 4; j++) {
                av[j] = *reinterpret_cast<const float4*>(&fa[(ng + 8 * j) * PADW + k]);
                xv[j] = *reinterpret_cast<const float4*>(&fx[(ng + 8 * j) * PADW + k]);
            }
            #pragma unroll
            for (int i = 0; i < 4; i++)
                #pragma unroll
                for (int j = 0; j < 4; j++) {
                    acc[i][j] += wl[i].x * av[j].x + wl[i].y * av[j].y
                               + wl[i].z * av[j].z + wl[i].w * av[j].w;
                    acc[i][j] += wr[i].x * xv[j].x + wr[i].y * xv[j].y
                               + wr[i].z * xv[j].z + wr[i].w * xv[j].w;
                }
        }
        __syncthreads();   // done reading fa/fx; reuse fa as h buffer

        // h[n][c] = relu(acc + bias); scalar stores, conflict-free (4*ng+cg distinct mod 32)
        #pragma unroll
        for (int j = 0; j < 4; j++)
            #pragma unroll
            for (int i = 0; i < 4; i++)
                fa[(ng + 8 * j) * PADW + (cg + 32 * i)] = fmaxf(acc[i][j] + bias[i], 0.f);
        __syncthreads();

        // z/s projection: warp wrp handles nodes 4*wrp .. 4*wrp+3
        #pragma unroll
        for (int q = 0; q < 4; q++) {
            int nl = wrp * 4 + q;
            int node = base + nl;
            float4 hv = *reinterpret_cast<const float4*>(&fa[nl * PADW + lane * 4]);
            float z0 = hv.x * a0.x + hv.y * a0.y + hv.z * a0.z + hv.w * a0.w;
            float z1 = hv.x * a1.x + hv.y * a1.y + hv.z * a1.z + hv.w * a1.w;
            float s0 = hv.x * bb0.x + hv.y * bb0.y + hv.z * bb0.z + hv.w * bb0.w;
            float s1 = hv.x * bb1.x + hv.y * bb1.y + hv.z * bb1.z + hv.w * bb1.w;
            #pragma unroll
            for (int off = 16; off > 0; off >>= 1) {
                z0 += __shfl_xor_sync(0xffffffffu, z0, off);
                z1 += __shfl_xor_sync(0xffffffffu, z1, off);
                s0 += __shfl_xor_sync(0xffffffffu, s0, off);
                s1 += __shfl_xor_sync(0xffffffffu, s1, off);
            }
            if (lane == 0 && node < n_nodes) {
                g_z[node * 2 + 0] = z0;
                g_z[node * 2 + 1] = z1;
                g_s[node * 2 + 0] = s0;
                g_s[node * 2 + 1] = s1;
            }
        }
        __syncthreads();   // before next group's feature load
    }
}

// -------- gather2 + epilogue: out = mean(z[src]) + s + c  (warp per node) --------
__global__ void gather2_kernel(float* __restrict__ out, int n_nodes) {
    int w = (blockIdx.x * blockDim.x + threadIdx.x) >> 5;
    int lane = threadIdx.x & 31;
    if (w >= n_nodes) return;
    int beg = g_rowptr[w];
    int end = g_rowptr[w + 1];
    float acc0 = 0.f, acc1 = 0.f;
    for (int j = beg + lane; j < end; j += 32) {
        int s = g_srcs[j];
        float2 zv = reinterpret_cast<const float2*>(g_z)[s];
        acc0 += zv.x;
        acc1 += zv.y;
    }
    #pragma unroll
    for (int off = 16; off > 0; off >>= 1) {
        acc0 += __shfl_xor_sync(0xffffffffu, acc0, off);
        acc1 += __shfl_xor_sync(0xffffffffu, acc1, off);
    }
    if (lane == 0) {
        float inv = 1.0f / (float)max(end - beg, 1);
        out[w * 2 + 0] = acc0 * inv + g_s[w * 2 + 0] + g_c[0];
        out[w * 2 + 1] = acc1 * inv + g_s[w * 2 + 1] + g_c[1];
    }
}

extern "C" void kernel_launch(void* const* d_in, const int* in_sizes, int n_in,
                              void* d_out, int out_size) {
    const float* x        = (const float*)d_in[0];
    const void*  ei       = d_in[1];
    const float* W1l      = (const float*)d_in[2];
    const float* b1       = (const float*)d_in[3];
    const float* W1r      = (const float*)d_in[4];
    const float* W2l      = (const float*)d_in[5];
    const float* b2       = (const float*)d_in[6];
    const float* W2r      = (const float*)d_in[7];
    const float* Wlin     = (const float*)d_in[8];
    const float* blin     = (const float*)d_in[9];
    float* out            = (float*)d_out;

    int n = in_sizes[0] / FEAT;       // 100000
    int E = in_sizes[1] / 2;          // 1600000
    int n_groups = (n + 31) / 32;
    int nb = (n + SCAN_BLK - 1) / SCAN_BLK;

    size_t smem = (size_t)(2 * FEAT * PADW + 2 * 32 * PADW) * sizeof(float);
    cudaFuncSetAttribute(dense1_kernel, cudaFuncAttributeMaxDynamicSharedMemorySize, (int)smem);

    detect_kernel<<<1, 32>>>((const int*)ei);
    prep_kernel<<<1, 256>>>(W2l, b2, W2r, Wlin, blin);
    zero_count_kernel<<<(n + 255) / 256, 256>>>(n);
    count_kernel<<<(E + 255) / 256, 256>>>(ei, E);
    scanA_kernel<<<nb, SCAN_BLK>>>(n);
    scanB_kernel<<<1, 128>>>(nb);
    scanC_kernel<<<nb, SCAN_BLK>>>(n, E);
    fill_kernel<<<(E + 255) / 256, 256>>>(ei, E);
    gather1_kernel<<<(n * 32 + 255) / 256, 256>>>(x, n);
    dense1_kernel<<<152, 256, smem>>>(x, W1l, b1, W1r, n, n_groups);
    gather2_kernel<<<(n * 32 + 255) / 256, 256>>>(out, n);
}

// round 7
// speedup vs baseline: 4.3236x; 1.6276x over previous
#include <cuda_runtime.h>
#include <cuda_bf16.h>
#include <cstdint>

#define NN 100000
#define EE 1600000
#define FEAT 128
#define SCAN_BLK 1024

// ---------------- device scratch ----------------
__device__ float g_agg[NN * FEAT];
__device__ float g_z[NN * 2];
__device__ float g_s[NN * 2];
__device__ float g_A[2 * FEAT];
__device__ float g_B[2 * FEAT];
__device__ float g_c[2];
__device__ int   g_is64;
__device__ int g_count[NN];
__device__ int g_rowptr[NN + 1];
__device__ int g_cursor[NN];
__device__ int g_bsum[128];
__device__ int g_boff[128];
__device__ int g_srcs[EE];

// ---------------- helpers ----------------
__device__ __forceinline__ uint32_t smem_u32(const void* p) {
    uint32_t a;
    asm("{ .reg .u64 t; cvta.to.shared.u64 t, %1; cvt.u32.u64 %0, t; }" : "=r"(a) : "l"(p));
    return a;
}
__device__ __forceinline__ void ldsm_x4(uint32_t& r0, uint32_t& r1, uint32_t& r2, uint32_t& r3,
                                        uint32_t addr) {
    asm volatile("ldmatrix.sync.aligned.m8n8.x4.shared.b16 {%0,%1,%2,%3}, [%4];"
                 : "=r"(r0), "=r"(r1), "=r"(r2), "=r"(r3) : "r"(addr));
}
__device__ __forceinline__ void mma16816(float* c, const uint32_t* a, const uint32_t* b) {
    asm volatile(
        "mma.sync.aligned.m16n8k16.row.col.f32.bf16.bf16.f32 "
        "{%0,%1,%2,%3}, {%4,%5,%6,%7}, {%8,%9}, {%0,%1,%2,%3};"
        : "+f"(c[0]), "+f"(c[1]), "+f"(c[2]), "+f"(c[3])
        : "r"(a[0]), "r"(a[1]), "r"(a[2]), "r"(a[3]), "r"(b[0]), "r"(b[1]));
}
__device__ __forceinline__ uint2 pack_hi(float4 v) {
    __nv_bfloat162 p01 = __floats2bfloat162_rn(v.x, v.y);
    __nv_bfloat162 p23 = __floats2bfloat162_rn(v.z, v.w);
    return make_uint2(*(uint32_t*)&p01, *(uint32_t*)&p23);
}
__device__ __forceinline__ uint2 pack_lo(float4 v) {
    __nv_bfloat162 p01 = __floats2bfloat162_rn(v.x, v.y);
    __nv_bfloat162 p23 = __floats2bfloat162_rn(v.z, v.w);
    float4 lo;
    lo.x = v.x - __bfloat162float(__low2bfloat16(p01));
    lo.y = v.y - __bfloat162float(__high2bfloat16(p01));
    lo.z = v.z - __bfloat162float(__low2bfloat16(p23));
    lo.w = v.w - __bfloat162float(__high2bfloat16(p23));
    __nv_bfloat162 q01 = __floats2bfloat162_rn(lo.x, lo.y);
    __nv_bfloat162 q23 = __floats2bfloat162_rn(lo.z, lo.w);
    return make_uint2(*(uint32_t*)&q01, *(uint32_t*)&q23);
}

// ---------------- small kernels ----------------
__global__ void detect_kernel(const int* __restrict__ ei32) {
    if (threadIdx.x == 0) {
        int orr = 0;
        #pragma unroll
        for (int i = 1; i < 32; i += 2) orr |= ei32[i];
        g_is64 = (orr == 0) ? 1 : 0;
    }
}
__device__ __forceinline__ int edge_at(const void* ei, int is64, long long idx) {
    if (is64) return (int)((const long long*)ei)[idx];
    return ((const int*)ei)[idx];
}
__global__ void prep_kernel(const float* __restrict__ W2l, const float* __restrict__ b2,
                            const float* __restrict__ W2r, const float* __restrict__ Wlin,
                            const float* __restrict__ blin) {
    int t = threadIdx.x;
    if (t < 256) {
        int o = t >> 7, f = t & 127;
        float a = 0.f, b = 0.f;
        #pragma unroll
        for (int k = 0; k < 4; k++) {
            float w = Wlin[o * 4 + k];
            a += w * W2l[k * FEAT + f];
            b += w * W2r[k * FEAT + f];
        }
        g_A[o * FEAT + f] = a;
        g_B[o * FEAT + f] = b;
    }
    if (t < 2) {
        float c = blin[t];
        #pragma unroll
        for (int k = 0; k < 4; k++) c += Wlin[t * 4 + k] * b2[k];
        g_c[t] = c;
    }
}
__global__ void zero_count_kernel(int n) {
    int i = blockIdx.x * blockDim.x + threadIdx.x;
    if (i < n) g_count[i] = 0;
}
__global__ void count_kernel(const void* __restrict__ ei, int E) {
    int e = blockIdx.x * blockDim.x + threadIdx.x;
    if (e >= E) return;
    int dst = edge_at(ei, g_is64, (long long)E + e);
    atomicAdd(&g_count[dst], 1);
}
__global__ void scanA_kernel(int n) {
    __shared__ int s[SCAN_BLK];
    int t = threadIdx.x;
    int idx = blockIdx.x * SCAN_BLK + t;
    int v = (idx < n) ? g_count[idx] : 0;
    s[t] = v;
    __syncthreads();
    for (int off = 1; off < SCAN_BLK; off <<= 1) {
        int u = (t >= off) ? s[t - off] : 0;
        __syncthreads();
        s[t] += u;
        __syncthreads();
    }
    if (idx <= n) g_rowptr[idx] = s[t] - v;
    if (t == SCAN_BLK - 1) g_bsum[blockIdx.x] = s[t];
}
__global__ void scanB_kernel(int nb) {
    __shared__ int s[128];
    int t = threadIdx.x;
    int v = (t < nb) ? g_bsum[t] : 0;
    s[t] = v;
    __syncthreads();
    for (int off = 1; off < 128; off <<= 1) {
        int u = (t >= off) ? s[t - off] : 0;
        __syncthreads();
        s[t] += u;
        __syncthreads();
    }
    if (t < nb) g_boff[t] = s[t] - v;
}
__global__ void scanC_kernel(int n, int E) {
    int idx = blockIdx.x * SCAN_BLK + threadIdx.x;
    int off = g_boff[blockIdx.x];
    if (idx < n) {
        int r = g_rowptr[idx] + off;
        g_rowptr[idx] = r;
        g_cursor[idx] = r;
    }
    if (idx == 0) g_rowptr[n] = E;
}
__global__ void fill_kernel(const void* __restrict__ ei, int E) {
    int e = blockIdx.x * blockDim.x + threadIdx.x;
    if (e >= E) return;
    int is64 = g_is64;
    int src = edge_at(ei, is64, e);
    int dst = edge_at(ei, is64, (long long)E + e);
    int slot = atomicAdd(&g_cursor[dst], 1);
    g_srcs[slot] = src;
}
__global__ void gather1_kernel(const float* __restrict__ x, int n_nodes) {
    int w = (blockIdx.x * blockDim.x + threadIdx.x) >> 5;
    int lane = threadIdx.x & 31;
    if (w >= n_nodes) return;
    int beg = g_rowptr[w];
    int end = g_rowptr[w + 1];
    float4 acc = make_float4(0.f, 0.f, 0.f, 0.f);
    for (int j0 = beg; j0 < end; j0 += 32) {
        int myid = (j0 + lane < end) ? g_srcs[j0 + lane] : 0;
        int cnt = min(32, end - j0);
        for (int k = 0; k < cnt; k++) {
            int s = __shfl_sync(0xffffffffu, myid, k);
            float4 v = reinterpret_cast<const float4*>(x)[(size_t)s * 32 + lane];
            acc.x += v.x; acc.y += v.y; acc.z += v.z; acc.w += v.w;
        }
    }
    float inv = 1.0f / (float)max(end - beg, 1);
    acc.x *= inv; acc.y *= inv; acc.z *= inv; acc.w *= inv;
    reinterpret_cast<float4*>(g_agg)[(size_t)w * 32 + lane] = acc;
}

// ---------------- mma.sync dense layer ----------------
// D[128 nodes][128 ch] = [agg|x](128x256) @ [W1l|W1r]^T(256x128), bf16 hi/lo 3-pass.
// smem rows padded to 264 bf16 (528B) -> ldmatrix conflict-free.
#define PAD_K 264
#define ROW_B (PAD_K * 2)        // 528 bytes
#define SM_A    0                // 128 * 528 = 67584
#define SM_BH   67584
#define SM_BL   135168
#define SM_BIAS 202752           // 128 floats
#define SM_PROJ 203264           // 128 float4
#define SM_ZS   205312           // 128 float4
#define SMEM_TOT 207360

__device__ __forceinline__ void mma_pass(uint32_t Abase, uint32_t Bbase,
                                         float c[2][8][4], int wm, int wn, int lane) {
    #pragma unroll 4
    for (int ks = 0; ks < 16; ks++) {
        int k = ks * 16;
        uint32_t a[2][4];
        #pragma unroll
        for (int mi = 0; mi < 2; mi++) {
            uint32_t addr = Abase + (uint32_t)((wm * 32 + mi * 16 + (lane & 15)) * ROW_B
                                             + (k + (lane >> 4) * 8) * 2);
            ldsm_x4(a[mi][0], a[mi][1], a[mi][2], a[mi][3], addr);
        }
        #pragma unroll
        for (int nq = 0; nq < 4; nq++) {
            uint32_t b[4];
            uint32_t addr = Bbase + (uint32_t)((wn * 64 + nq * 16 + (lane & 7) + ((lane >> 4) << 3)) * ROW_B
                                             + (k + ((lane >> 3) & 1) * 8) * 2);
            ldsm_x4(b[0], b[1], b[2], b[3], addr);
            #pragma unroll
            for (int mi = 0; mi < 2; mi++) {
                mma16816(c[mi][nq * 2 + 0], a[mi], b + 0);
                mma16816(c[mi][nq * 2 + 1], a[mi], b + 2);
            }
        }
    }
}

__global__ void __launch_bounds__(256, 1)
dense_mma_kernel(const float* __restrict__ x,
                 const float* __restrict__ W1l,
                 const float* __restrict__ b1,
                 const float* __restrict__ W1r,
                 int n_nodes, int n_tiles) {
    extern __shared__ char smem[];
    uint32_t sb = smem_u32(smem);
    int tid = threadIdx.x;
    int wid = tid >> 5, lane = tid & 31;
    int wm = wid & 3, wn = wid >> 2;

    float* sbias = (float*)(smem + SM_BIAS);
    float4* sproj = (float4*)(smem + SM_PROJ);
    float4* szs = (float4*)(smem + SM_ZS);

    // stage bias + projection
    if (tid < 128) {
        sbias[tid] = b1[tid];
        sproj[tid] = make_float4(g_A[tid], g_A[128 + tid], g_B[tid], g_B[128 + tid]);
    }
    // stage B hi/lo: row = channel, cols 0-127 = W1l, 128-255 = W1r
    for (int r = wid; r < 128; r += 8) {
        float4 w1 = reinterpret_cast<const float4*>(W1l)[r * 32 + lane];
        float4 w2 = reinterpret_cast<const float4*>(W1r)[r * 32 + lane];
        *(uint2*)(smem + SM_BH + r * ROW_B + (4 * lane) * 2) = pack_hi(w1);
        *(uint2*)(smem + SM_BL + r * ROW_B + (4 * lane) * 2) = pack_lo(w1);
        *(uint2*)(smem + SM_BH + r * ROW_B + (128 + 4 * lane) * 2) = pack_hi(w2);
        *(uint2*)(smem + SM_BL + r * ROW_B + (128 + 4 * lane) * 2) = pack_lo(w2);
    }
    __syncthreads();

    uint32_t Ab = sb + SM_A, BHb = sb + SM_BH, BLb = sb + SM_BL;

    for (int tile = blockIdx.x; tile < n_tiles; tile += gridDim.x) {
        int base = tile * 128;

        // ---- stage A_hi ----
        for (int n = wid; n < 128; n += 8) {
            int node = base + n;
            float4 va = make_float4(0.f, 0.f, 0.f, 0.f), vx = va;
            if (node < n_nodes) {
                va = reinterpret_cast<const float4*>(g_agg)[(size_t)node * 32 + lane];
                vx = reinterpret_cast<const float4*>(x)[(size_t)node * 32 + lane];
            }
            *(uint2*)(smem + SM_A + n * ROW_B + (4 * lane) * 2) = pack_hi(va);
            *(uint2*)(smem + SM_A + n * ROW_B + (128 + 4 * lane) * 2) = pack_hi(vx);
        }
        __syncthreads();

        float c[2][8][4];
        #pragma unroll
        for (int i = 0; i < 2; i++)
            #pragma unroll
            for (int j = 0; j < 8; j++)
                #pragma unroll
                for (int v = 0; v < 4; v++) c[i][j][v] = 0.f;

        mma_pass(Ab, BHb, c, wm, wn, lane);   // Ah * Bh
        mma_pass(Ab, BLb, c, wm, wn, lane);   // Ah * Bl
        __syncthreads();

        // ---- overwrite A with A_lo ----
        for (int n = wid; n < 128; n += 8) {
            int node = base + n;
            float4 va = make_float4(0.f, 0.f, 0.f, 0.f), vx = va;
            if (node < n_nodes) {
                va = reinterpret_cast<const float4*>(g_agg)[(size_t)node * 32 + lane];
                vx = reinterpret_cast<const float4*>(x)[(size_t)node * 32 + lane];
            }
            *(uint2*)(smem + SM_A + n * ROW_B + (4 * lane) * 2) = pack_lo(va);
            *(uint2*)(smem + SM_A + n * ROW_B + (128 + 4 * lane) * 2) = pack_lo(vx);
        }
        __syncthreads();

        mma_pass(Ab, BHb, c, wm, wn, lane);   // Al * Bh

        // ---- epilogue: bias + relu + z/s projection ----
        float zp[4][4];
        #pragma unroll
        for (int r = 0; r < 4; r++)
            #pragma unroll
            for (int v = 0; v < 4; v++) zp[r][v] = 0.f;

        #pragma unroll
        for (int f = 0; f < 8; f++) {
            int ch0 = wn * 64 + f * 8 + (lane & 3) * 2;
            float b0 = sbias[ch0], b1v = sbias[ch0 + 1];
            float4 p0 = sproj[ch0], p1 = sproj[ch0 + 1];
            #pragma unroll
            for (int mi = 0; mi < 2; mi++) {
                float h00 = fmaxf(c[mi][f][0] + b0, 0.f);
                float h01 = fmaxf(c[mi][f][1] + b1v, 0.f);
                float h10 = fmaxf(c[mi][f][2] + b0, 0.f);
                float h11 = fmaxf(c[mi][f][3] + b1v, 0.f);
                int r0 = mi * 2, r1 = mi * 2 + 1;
                zp[r0][0] += h00 * p0.x + h01 * p1.x;
                zp[r0][1] += h00 * p0.y + h01 * p1.y;
                zp[r0][2] += h00 * p0.z + h01 * p1.z;
                zp[r0][3] += h00 * p0.w + h01 * p1.w;
                zp[r1][0] += h10 * p0.x + h11 * p1.x;
                zp[r1][1] += h10 * p0.y + h11 * p1.y;
                zp[r1][2] += h10 * p0.z + h11 * p1.z;
                zp[r1][3] += h10 * p0.w + h11 * p1.w;
            }
        }
        // reduce across the 4 lanes sharing a row
        #pragma unroll
        for (int r = 0; r < 4; r++)
            #pragma unroll
            for (int v = 0; v < 4; v++) {
                zp[r][v] += __shfl_xor_sync(0xffffffffu, zp[r][v], 1);
                zp[r][v] += __shfl_xor_sync(0xffffffffu, zp[r][v], 2);
            }

        // cross-warp_n combine via smem
        if (wn == 0 && (lane & 3) == 0) {
            #pragma unroll
            for (int r = 0; r < 4; r++) {
                int row = wm * 32 + (r >> 1) * 16 + (r & 1) * 8 + (lane >> 2);
                szs[row] = make_float4(zp[r][0], zp[r][1], zp[r][2], zp[r][3]);
            }
        }
        __syncthreads();
        if (wn == 1 && (lane & 3) == 0) {
            #pragma unroll
            for (int r = 0; r < 4; r++) {
                int row = wm * 32 + (r >> 1) * 16 + (r & 1) * 8 + (lane >> 2);
                float4 o = szs[row];
                int node = base + row;
                if (node < n_nodes) {
                    *(float2*)&g_z[node * 2] = make_float2(o.x + zp[r][0], o.y + zp[r][1]);
                    *(float2*)&g_s[node * 2] = make_float2(o.z + zp[r][2], o.w + zp[r][3]);
                }
            }
        }
        __syncthreads();
    }
}

// ---------------- gather2 + epilogue ----------------
__global__ void gather2_kernel(float* __restrict__ out, int n_nodes) {
    int w = (blockIdx.x * blockDim.x + threadIdx.x) >> 5;
    int lane = threadIdx.x & 31;
    if (w >= n_nodes) return;
    int beg = g_rowptr[w];
    int end = g_rowptr[w + 1];
    float acc0 = 0.f, acc1 = 0.f;
    for (int j = beg + lane; j < end; j += 32) {
        int s = g_srcs[j];
        float2 zv = reinterpret_cast<const float2*>(g_z)[s];
        acc0 += zv.x;
        acc1 += zv.y;
    }
    #pragma unroll
    for (int off = 16; off > 0; off >>= 1) {
        acc0 += __shfl_xor_sync(0xffffffffu, acc0, off);
        acc1 += __shfl_xor_sync(0xffffffffu, acc1, off);
    }
    if (lane == 0) {
        float inv = 1.0f / (float)max(end - beg, 1);
        out[w * 2 + 0] = acc0 * inv + g_s[w * 2 + 0] + g_c[0];
        out[w * 2 + 1] = acc1 * inv + g_s[w * 2 + 1] + g_c[1];
    }
}

extern "C" void kernel_launch(void* const* d_in, const int* in_sizes, int n_in,
                              void* d_out, int out_size) {
    const float* x        = (const float*)d_in[0];
    const void*  ei       = d_in[1];
    const float* W1l      = (const float*)d_in[2];
    const float* b1       = (const float*)d_in[3];
    const float* W1r      = (const float*)d_in[4];
    const float* W2l      = (const float*)d_in[5];
    const float* b2       = (const float*)d_in[6];
    const float* W2r      = (const float*)d_in[7];
    const float* Wlin     = (const float*)d_in[8];
    const float* blin     = (const float*)d_in[9];
    float* out            = (float*)d_out;

    int n = in_sizes[0] / FEAT;
    int E = in_sizes[1] / 2;
    int n_tiles = (n + 127) / 128;
    int nb = (n + SCAN_BLK - 1) / SCAN_BLK;

    cudaFuncSetAttribute(dense_mma_kernel, cudaFuncAttributeMaxDynamicSharedMemorySize, SMEM_TOT);

    detect_kernel<<<1, 32>>>((const int*)ei);
    prep_kernel<<<1, 256>>>(W2l, b2, W2r, Wlin, blin);
    zero_count_kernel<<<(n + 255) / 256, 256>>>(n);
    count_kernel<<<(E + 255) / 256, 256>>>(ei, E);
    scanA_kernel<<<nb, SCAN_BLK>>>(n);
    scanB_kernel<<<1, 128>>>(nb);
    scanC_kernel<<<nb, SCAN_BLK>>>(n, E);
    fill_kernel<<<(E + 255) / 256, 256>>>(ei, E);
    gather1_kernel<<<(n * 32 + 255) / 256, 256>>>(x, n);
    dense_mma_kernel<<<152, 256, SMEM_TOT>>>(x, W1l, b1, W1r, n, n_tiles);
    gather2_kernel<<<(n * 32 + 255) / 256, 256>>>(out, n);
}